// round 5
// baseline (speedup 1.0000x reference)
#include <cuda_runtime.h>
#include <cuda_fp16.h>
#include <cstdint>

// ---------------------------------------------------------------------------
// Problem constants
// ---------------------------------------------------------------------------
#define B_DIM 32
#define W_DIM 16
#define N_DIM 256

// Materialized weight tensor: Wgh[w][s][m][n] in fp16. 8.4 MB, L2-resident.
__device__ __half g_Wgh[W_DIM * 4 * N_DIM * N_DIM];

// ---------------------------------------------------------------------------
// Kernel 1: Wgh[w][s][m][n] = fp16(bias_table[rel_index[m][n], s*16+w])
// ---------------------------------------------------------------------------
__global__ __launch_bounds__(256) void build_weights(
    const float* __restrict__ bias_table, const int* __restrict__ rel_index)
{
    __shared__ float tile[128][65];
    __shared__ int rels[128];
    const int m  = blockIdx.x;
    const int n0 = blockIdx.y * 128;
    const int tid = threadIdx.x;

    if (tid < 128) rels[tid] = rel_index[m * N_DIM + n0 + tid];
    __syncthreads();

#pragma unroll
    for (int i = 0; i < 32; i++) {
        int u = tid + i * 256;
        int n = u >> 6, c = u & 63;
        tile[n][c] = bias_table[rels[n] * 64 + c];
    }
    __syncthreads();

    // Scatter as half2 (two n per thread), coalesced.
    __half2* g2 = reinterpret_cast<__half2*>(g_Wgh);
#pragma unroll
    for (int i = 0; i < 16; i++) {
        int u = tid + i * 256;
        int c = u >> 6, n2 = u & 63;
        int wq = c & 15, s = c >> 4;
        g2[(((wq * 4 + s) * N_DIM + m) << 7) + (n0 >> 1) + n2] =
            __floats2half2_rn(tile[2 * n2][c], tile[2 * n2 + 1][c]);
    }
}

// ---------------------------------------------------------------------------
// MMA / ldmatrix helpers
// ---------------------------------------------------------------------------
__device__ __forceinline__ void ldsm_x4(uint32_t* r, uint32_t addr) {
    asm volatile("ldmatrix.sync.aligned.m8n8.x4.shared.b16 {%0,%1,%2,%3}, [%4];"
        : "=r"(r[0]), "=r"(r[1]), "=r"(r[2]), "=r"(r[3]) : "r"(addr));
}
__device__ __forceinline__ void ldsm_x4_t(uint32_t* r, uint32_t addr) {
    asm volatile("ldmatrix.sync.aligned.m8n8.x4.trans.shared.b16 {%0,%1,%2,%3}, [%4];"
        : "=r"(r[0]), "=r"(r[1]), "=r"(r[2]), "=r"(r[3]) : "r"(addr));
}
__device__ __forceinline__ void hmma(float* d, const uint32_t* a, uint32_t b0, uint32_t b1) {
    asm volatile(
        "mma.sync.aligned.m16n8k16.row.col.f32.f16.f16.f32 "
        "{%0,%1,%2,%3},{%4,%5,%6,%7},{%8,%9},{%0,%1,%2,%3};"
        : "+f"(d[0]), "+f"(d[1]), "+f"(d[2]), "+f"(d[3])
        : "r"(a[0]), "r"(a[1]), "r"(a[2]), "r"(a[3]), "r"(b0), "r"(b1));
}
__device__ __forceinline__ uint32_t pack_h2(float lo, float hi) {
    __half2 h = __floats2half2_rn(lo, hi);
    return *reinterpret_cast<uint32_t*>(&h);
}
__device__ __forceinline__ uint32_t smem_u32(const void* p) {
    uint32_t a;
    asm("{ .reg .u64 t; cvta.to.shared.u64 t, %1; cvt.u32.u64 %0, t; }"
        : "=r"(a) : "l"(p));
    return a;
}

// ---------------------------------------------------------------------------
// Kernel 2: CTA=(b, w, m_half, s_pair): OUT tile M=128 x 128 cols (2 s-planes
// x 64 v). 256 threads / 8 warps, __launch_bounds__(256,2) -> 2 CTAs/SM.
// K chunks of 32, double-buffered, XOR-swizzled LDSM layouts (as R4):
//   A: [p<2][m 128][32k] fp16, row 64B, swizzle q ^= (m>>1)&3
//   X: [p<2][k 32][64v] fp16, row 128B, swizzle c ^= k&7
// ---------------------------------------------------------------------------
#define AS_PLANE 8192
#define A_STAGE  16384
#define XS_PLANE 4096
#define X_STAGE  8192
#define STAGE_BYTES (A_STAGE + X_STAGE)         // 24576
#define OUT_PITCH 130
#define SMEM_DYN (128 * OUT_PITCH * 4)          // 66560 (> 2*STAGE_BYTES)

__global__ __launch_bounds__(256, 2) void pos_map_mm(
    const float* __restrict__ x, const float* __restrict__ token_bias,
    float* __restrict__ out)
{
    extern __shared__ __align__(16) char smem[];
    const int b = blockIdx.x, w = blockIdx.y;
    const int m0 = (blockIdx.z >> 1) * 128;
    const int sh = blockIdx.z & 1;               // s-pair: s in {2sh, 2sh+1}
    const int tid = threadIdx.x, lane = tid & 31, warp = tid >> 5;
    const int wm = warp & 3;    // m-group: 32 rows
    const int wc = warp >> 2;   // s within pair: 0/1
    const uint32_t sbase = smem_u32(smem);

    const __half* WgBase = g_Wgh + (size_t)(w * 4 + sh * 2) * 65536
                         + (size_t)m0 * 256;
    const float4* xb4 = (const float4*)x + (size_t)(b * 16 + w) * (256 * 64);

    float acc[2][8][4];
#pragma unroll
    for (int mt = 0; mt < 2; mt++)
#pragma unroll
        for (int nt = 0; nt < 8; nt++)
#pragma unroll
            for (int j = 0; j < 4; j++) acc[mt][nt][j] = 0.f;

    uint32_t xh[4][2];   // prefetched X for next chunk: [iter][s_local]

    // Per-lane LDSM geometry
    const int grp  = lane >> 3;
    const int row8 = (grp & 1) * 8 + (lane & 7);
    const int qsel = grp >> 1;

    auto issue_A = [&](int st, int n0c) {
#pragma unroll
        for (int i = 0; i < 4; i++) {
            int u = tid + i * 256;                 // 1024 x 16B
            int p = u >> 9, r = (u >> 2) & 127, q = u & 3;
            const __half* src = WgBase + p * 65536 + r * 256 + n0c + q * 8;
            uint32_t dst = sbase + st * STAGE_BYTES + p * AS_PLANE + r * 64
                         + ((q ^ ((r >> 1) & 3)) << 4);
            asm volatile("cp.async.cg.shared.global [%0], [%1], 16;"
                         :: "r"(dst), "l"(src));
        }
        asm volatile("cp.async.commit_group;");
    };
    auto load_X = [&](int n0c) {
#pragma unroll
        for (int it = 0; it < 4; it++) {
            int u = tid + it * 256;                // 1024 (k, vpair) units
            int vp = u & 31, k = u >> 5;
            float4 f0 = xb4[(n0c + k) * 64 + 2 * vp];
            float4 f1 = xb4[(n0c + k) * 64 + 2 * vp + 1];
            const float* a0 = &f0.x;
            const float* a1 = &f1.x;
            xh[it][0] = pack_h2(a0[2 * sh],     a1[2 * sh]);
            xh[it][1] = pack_h2(a0[2 * sh + 1], a1[2 * sh + 1]);
        }
    };
    auto store_X = [&](int st) {
        char* xs = smem + st * STAGE_BYTES + A_STAGE;
#pragma unroll
        for (int it = 0; it < 4; it++) {
            int u = tid + it * 256;
            int vp = u & 31, k = u >> 5;
            int off = k * 128 + (((vp >> 2) ^ (k & 7)) << 4) + ((vp & 3) << 2);
            *(uint32_t*)(xs + 0 * XS_PLANE + off) = xh[it][0];
            *(uint32_t*)(xs + 1 * XS_PLANE + off) = xh[it][1];
        }
    };
    auto compute = [&](int st) {
        const uint32_t sA = sbase + st * STAGE_BYTES + wc * AS_PLANE;
        const uint32_t sX = sbase + st * STAGE_BYTES + A_STAGE + wc * XS_PLANE;
#pragma unroll
        for (int ks = 0; ks < 2; ks++) {
            uint32_t a[2][4];
#pragma unroll
            for (int mt = 0; mt < 2; mt++) {
                int m = wm * 32 + mt * 16 + row8;
                int q = ks * 2 + qsel;
                ldsm_x4(a[mt], sA + m * 64 + ((q ^ ((m >> 1) & 3)) << 4));
            }
            uint32_t bq[4][4];
#pragma unroll
            for (int ng = 0; ng < 4; ng++) {
                int k = ks * 16 + row8;
                int c = ng * 2 + qsel;
                ldsm_x4_t(bq[ng], sX + k * 128 + ((c ^ (k & 7)) << 4));
            }
#pragma unroll
            for (int mt = 0; mt < 2; mt++)
#pragma unroll
                for (int nt = 0; nt < 8; nt++)
                    hmma(acc[mt][nt], a[mt],
                         bq[nt >> 1][(nt & 1) * 2], bq[nt >> 1][(nt & 1) * 2 + 1]);
        }
    };

    // ---- prologue: chunk 0 ----
    issue_A(0, 0);
    load_X(0);
    store_X(0);
    asm volatile("cp.async.wait_group 0;");
    __syncthreads();

    // ---- main loop over 8 K-chunks ----
    for (int ch = 0; ch < 8; ch++) {
        const int st = ch & 1, nx = (ch + 1) & 1;
        if (ch < 7) {
            issue_A(nx, (ch + 1) * 32);
            load_X((ch + 1) * 32);
        }
        compute(st);
        if (ch < 7) store_X(nx);
        asm volatile("cp.async.wait_group 0;");
        __syncthreads();
    }

    // ---- epilogue: bias add, smem stage, float2 coalesced store ----
    float* so = (float*)smem;   // [128][OUT_PITCH]; col index = 2v + wc
    {
        float tb0 = token_bias[(w * 4 + sh * 2 + wc) * 256 + m0
                               + wm * 32 + (lane >> 2)];
        (void)tb0;
    }
#pragma unroll
    for (int mt = 0; mt < 2; mt++)
#pragma unroll
        for (int j = 0; j < 2; j++) {
            int m = wm * 32 + mt * 16 + (lane >> 2) + j * 8;
            float tb = token_bias[(w * 4 + sh * 2 + wc) * 256 + m0 + m];
            float* dr = so + m * OUT_PITCH + wc;
#pragma unroll
            for (int nt = 0; nt < 8; nt++) {
                int v = nt * 8 + ((lane & 3) << 1);
                dr[2 * v]       = acc[mt][nt][j * 2 + 0] + tb;
                dr[2 * (v + 1)] = acc[mt][nt][j * 2 + 1] + tb;
            }
        }
    __syncthreads();

    // out cols for this CTA: d = 4v + 2sh + {0,1} -> float2 at 4v+2sh
    float* ob = out + (size_t)((b * 16 + w) * 256 + m0) * 256 + 2 * sh;
#pragma unroll
    for (int i = 0; i < 32; i++) {
        int u = tid + i * 256;
        int row = u >> 6, vv = u & 63;
        *(float2*)(ob + row * 256 + 4 * vv) =
            *(float2*)(so + row * OUT_PITCH + 2 * vv);
    }
}

// ---------------------------------------------------------------------------
// Launch: inputs in metadata order: x, bias_table, token_bias, rel_index
// ---------------------------------------------------------------------------
extern "C" void kernel_launch(void* const* d_in, const int* in_sizes, int n_in,
                              void* d_out, int out_size)
{
    const float* x          = (const float*)d_in[0];
    const float* bias_table = (const float*)d_in[1];
    const float* token_bias = (const float*)d_in[2];
    const int*   rel_index  = (const int*)d_in[3];
    float* out = (float*)d_out;
    (void)in_sizes; (void)n_in; (void)out_size;

    cudaFuncSetAttribute(pos_map_mm,
                         cudaFuncAttributeMaxDynamicSharedMemorySize, SMEM_DYN);

    build_weights<<<dim3(256, 2), 256>>>(bias_table, rel_index);
    pos_map_mm<<<dim3(B_DIM, W_DIM, 4), 256, SMEM_DYN>>>(x, token_bias, out);
}

// round 6
// speedup vs baseline: 1.6201x; 1.6201x over previous
#include <cuda_runtime.h>
#include <cuda_fp16.h>
#include <cstdint>

// ---------------------------------------------------------------------------
// Problem constants
// ---------------------------------------------------------------------------
#define B_DIM 32
#define W_DIM 16
#define N_DIM 256

// Wgh[w][s][m][n] fp16 weights (8.4 MB) + Xt[b][w][s][n][v] fp16 x (67 MB).
__device__ __half  g_Wgh[W_DIM * 4 * N_DIM * N_DIM];
__device__ __half2 g_Xt2[B_DIM * W_DIM * 4 * N_DIM * 32];

// ---------------------------------------------------------------------------
// Prep kernel (merged): bx < 2048 -> transpose x to Xt; else build Wgh.
// ---------------------------------------------------------------------------
__global__ __launch_bounds__(256) void prep(
    const float* __restrict__ x,
    const float* __restrict__ bias_table, const int* __restrict__ rel_index)
{
    __shared__ float tile[128][65];
    __shared__ int rels[128];
    const int bx = blockIdx.x, tid = threadIdx.x;

    if (bx < 2048) {
        // ---- x transpose: CTA = (b, w, n-quarter) ----
        const int q = bx & 3, w = (bx >> 2) & 15, b = bx >> 6;
        const int n0 = q * 64;
        const float4* xb4 = (const float4*)x + (size_t)(b * 16 + w) * (256 * 64);
        __half2* xt = g_Xt2 + (size_t)(b * 16 + w) * 4 * 8192;
#pragma unroll
        for (int i = 0; i < 8; i++) {
            int u = tid + i * 256;             // 64 n x 32 vp
            int vp = u & 31, n = n0 + (u >> 5);
            float4 f0 = xb4[n * 64 + 2 * vp];
            float4 f1 = xb4[n * 64 + 2 * vp + 1];
            const float* p0 = reinterpret_cast<const float*>(&f0);
            const float* p1 = reinterpret_cast<const float*>(&f1);
#pragma unroll
            for (int s = 0; s < 4; s++)
                xt[s * 8192 + n * 32 + vp] = __floats2half2_rn(p0[s], p1[s]);
        }
        return;
    }

    // ---- weight build: r = (m, n-half) ----
    const int r = bx - 2048;
    const int m = r >> 1, n0 = (r & 1) * 128;

    if (tid < 128) rels[tid] = rel_index[m * N_DIM + n0 + tid];
    __syncthreads();

#pragma unroll
    for (int i = 0; i < 32; i++) {
        int u = tid + i * 256;
        int n = u >> 6, c = u & 63;
        tile[n][c] = bias_table[rels[n] * 64 + c];
    }
    __syncthreads();

    __half2* g2 = reinterpret_cast<__half2*>(g_Wgh);
#pragma unroll
    for (int i = 0; i < 16; i++) {
        int u = tid + i * 256;
        int c = u >> 6, n2 = u & 63;
        int wq = c & 15, s = c >> 4;
        g2[(((wq * 4 + s) * N_DIM + m) << 7) + (n0 >> 1) + n2] =
            __floats2half2_rn(tile[2 * n2][c], tile[2 * n2 + 1][c]);
    }
}

// ---------------------------------------------------------------------------
// MMA / ldmatrix helpers
// ---------------------------------------------------------------------------
__device__ __forceinline__ void ldsm_x4(uint32_t* r, uint32_t addr) {
    asm volatile("ldmatrix.sync.aligned.m8n8.x4.shared.b16 {%0,%1,%2,%3}, [%4];"
        : "=r"(r[0]), "=r"(r[1]), "=r"(r[2]), "=r"(r[3]) : "r"(addr));
}
__device__ __forceinline__ void ldsm_x4_t(uint32_t* r, uint32_t addr) {
    asm volatile("ldmatrix.sync.aligned.m8n8.x4.trans.shared.b16 {%0,%1,%2,%3}, [%4];"
        : "=r"(r[0]), "=r"(r[1]), "=r"(r[2]), "=r"(r[3]) : "r"(addr));
}
__device__ __forceinline__ void hmma(float* d, const uint32_t* a, uint32_t b0, uint32_t b1) {
    asm volatile(
        "mma.sync.aligned.m16n8k16.row.col.f32.f16.f16.f32 "
        "{%0,%1,%2,%3},{%4,%5,%6,%7},{%8,%9},{%0,%1,%2,%3};"
        : "+f"(d[0]), "+f"(d[1]), "+f"(d[2]), "+f"(d[3])
        : "r"(a[0]), "r"(a[1]), "r"(a[2]), "r"(a[3]), "r"(b0), "r"(b1));
}
__device__ __forceinline__ uint32_t smem_u32(const void* p) {
    uint32_t a;
    asm("{ .reg .u64 t; cvta.to.shared.u64 t, %1; cvt.u32.u64 %0, t; }"
        : "=r"(a) : "l"(p));
    return a;
}

// ---------------------------------------------------------------------------
// Main kernel: CTA = bx -> (mh = bx&1, w = (bx>>1)&15, b = bx>>5).
// OUT tile M=128 x D=256 (4 s x 64 v). 512 thr. K chunks of 64, 2 stages,
// both operands via cp.async from prebuilt fp16 tensors.
//   A: [s][m 128][64k] rows 128B, swizzle q ^= m&7
//   X: [s][k 64][64v] rows 128B, swizzle c ^= k&7
// ---------------------------------------------------------------------------
#define AS_PLANE 16384
#define A_STAGE  65536
#define XS_PLANE 8192
#define X_STAGE  32768
#define STAGE_BYTES (A_STAGE + X_STAGE)      // 98304
#define OUT_PITCH 260
#define SMEM_DYN (2 * STAGE_BYTES)           // 196608

__global__ __launch_bounds__(512, 1) void pos_map_mm(
    const float* __restrict__ token_bias, float* __restrict__ out)
{
    extern __shared__ __align__(16) char smem[];
    const int bx = blockIdx.x;
    const int m0 = (bx & 1) * 128, w = (bx >> 1) & 15, b = bx >> 5;
    const int tid = threadIdx.x, lane = tid & 31, warp = tid >> 5;
    const int wm = warp & 3;    // m-group: 32 rows
    const int wc = warp >> 2;   // s-plane
    const uint32_t sbase = smem_u32(smem);

    const __half* WgBase = g_Wgh + (size_t)(w * 4) * 65536 + (size_t)m0 * 256;
    const __half* XtBase = reinterpret_cast<const __half*>(g_Xt2)
                         + (size_t)(b * 16 + w) * 4 * 16384;

    float acc[2][8][4];
#pragma unroll
    for (int mt = 0; mt < 2; mt++)
#pragma unroll
        for (int nt = 0; nt < 8; nt++)
#pragma unroll
            for (int j = 0; j < 4; j++) acc[mt][nt][j] = 0.f;

    const int grp  = lane >> 3;
    const int row8 = (grp & 1) * 8 + (lane & 7);
    const int qsel = grp >> 1;

    auto issue_chunk = [&](int st, int n0c) {
        // A: 4096 x 16B units (4s x 128m x 8q)
#pragma unroll
        for (int i = 0; i < 8; i++) {
            int u = tid + i * 512;
            int s = u >> 10, m = (u >> 3) & 127, q = u & 7;
            const __half* src = WgBase + s * 65536 + m * 256 + n0c + q * 8;
            uint32_t dst = sbase + st * STAGE_BYTES + s * AS_PLANE + m * 128
                         + ((q ^ (m & 7)) << 4);
            asm volatile("cp.async.cg.shared.global [%0], [%1], 16;"
                         :: "r"(dst), "l"(src));
        }
        // X: 2048 x 16B units (4s x 64k x 8c)
#pragma unroll
        for (int i = 0; i < 4; i++) {
            int u = tid + i * 512;
            int s = u >> 9, k = (u >> 3) & 63, c = u & 7;
            const __half* src = XtBase + s * 16384 + (n0c + k) * 64 + c * 8;
            uint32_t dst = sbase + st * STAGE_BYTES + A_STAGE + s * XS_PLANE
                         + k * 128 + ((c ^ (k & 7)) << 4);
            asm volatile("cp.async.cg.shared.global [%0], [%1], 16;"
                         :: "r"(dst), "l"(src));
        }
        asm volatile("cp.async.commit_group;");
    };

    auto compute = [&](int st) {
        const uint32_t sA = sbase + st * STAGE_BYTES + wc * AS_PLANE;
        const uint32_t sX = sbase + st * STAGE_BYTES + A_STAGE + wc * XS_PLANE;
#pragma unroll
        for (int ks = 0; ks < 4; ks++) {
            uint32_t a[2][4];
#pragma unroll
            for (int mt = 0; mt < 2; mt++) {
                int m = wm * 32 + mt * 16 + row8;
                int q = ks * 2 + qsel;
                ldsm_x4(a[mt], sA + m * 128 + ((q ^ (m & 7)) << 4));
            }
            uint32_t bq[4][4];
#pragma unroll
            for (int ng = 0; ng < 4; ng++) {
                int k = ks * 16 + row8;
                int c = ng * 2 + qsel;
                ldsm_x4_t(bq[ng], sX + k * 128 + ((c ^ (k & 7)) << 4));
            }
#pragma unroll
            for (int mt = 0; mt < 2; mt++)
#pragma unroll
                for (int nt = 0; nt < 8; nt++)
                    hmma(acc[mt][nt], a[mt],
                         bq[nt >> 1][(nt & 1) * 2], bq[nt >> 1][(nt & 1) * 2 + 1]);
        }
    };

    // ---- prologue ----
    issue_chunk(0, 0);
    asm volatile("cp.async.wait_group 0;");
    __syncthreads();

    // ---- main loop: 4 K-chunks of 64 ----
    for (int ch = 0; ch < 4; ch++) {
        const int st = ch & 1;
        if (ch < 3) issue_chunk((ch + 1) & 1, (ch + 1) * 64);
        compute(st);
        asm volatile("cp.async.wait_group 0;");
        __syncthreads();
    }

    // ---- epilogue: bias add, smem stage, coalesced float4 store ----
    float* so = (float*)smem;   // [128][OUT_PITCH]
#pragma unroll
    for (int mt = 0; mt < 2; mt++)
#pragma unroll
        for (int j = 0; j < 2; j++) {
            int m = wm * 32 + mt * 16 + (lane >> 2) + j * 8;
            float tb = token_bias[(w * 4 + wc) * 256 + m0 + m];
            float* dr = so + m * OUT_PITCH + wc;
#pragma unroll
            for (int nt = 0; nt < 8; nt++) {
                int v = nt * 8 + ((lane & 3) << 1);
                dr[v * 4]       = acc[mt][nt][j * 2 + 0] + tb;
                dr[(v + 1) * 4] = acc[mt][nt][j * 2 + 1] + tb;
            }
        }
    __syncthreads();

    float4* ob = (float4*)(out + (size_t)((b * 16 + w) * 256 + m0) * 256);
#pragma unroll
    for (int i = 0; i < 16; i++) {
        int u = tid + i * 512;
        int row = u >> 6, c = u & 63;
        ob[row * 64 + c] = *(float4*)(so + row * OUT_PITCH + c * 4);
    }
}

// ---------------------------------------------------------------------------
// Launch: inputs in metadata order: x, bias_table, token_bias, rel_index
// ---------------------------------------------------------------------------
extern "C" void kernel_launch(void* const* d_in, const int* in_sizes, int n_in,
                              void* d_out, int out_size)
{
    const float* x          = (const float*)d_in[0];
    const float* bias_table = (const float*)d_in[1];
    const float* token_bias = (const float*)d_in[2];
    const int*   rel_index  = (const int*)d_in[3];
    float* out = (float*)d_out;
    (void)in_sizes; (void)n_in; (void)out_size;

    cudaFuncSetAttribute(pos_map_mm,
                         cudaFuncAttributeMaxDynamicSharedMemorySize, SMEM_DYN);

    prep<<<2560, 256>>>(x, bias_table, rel_index);
    pos_map_mm<<<1024, 512, SMEM_DYN>>>(token_bias, out);
}

// round 7
// speedup vs baseline: 1.7800x; 1.0987x over previous
#include <cuda_runtime.h>
#include <cuda_fp16.h>
#include <cstdint>

// ---------------------------------------------------------------------------
// Problem constants
// ---------------------------------------------------------------------------
#define B_DIM 32
#define W_DIM 16
#define N_DIM 256

// Wgh[w][s][m][n] fp16 weights (8.4 MB), L2-resident.
__device__ __half g_Wgh[W_DIM * 4 * N_DIM * N_DIM];

// ---------------------------------------------------------------------------
// Kernel 1: Wgh[w][s][m][n] = fp16(bias_table[rel_index[m][n], s*16+w])
// ---------------------------------------------------------------------------
__global__ __launch_bounds__(256) void build_weights(
    const float* __restrict__ bias_table, const int* __restrict__ rel_index)
{
    __shared__ float tile[128][65];
    __shared__ int rels[128];
    const int m  = blockIdx.x;
    const int n0 = blockIdx.y * 128;
    const int tid = threadIdx.x;

    if (tid < 128) rels[tid] = rel_index[m * N_DIM + n0 + tid];
    __syncthreads();

#pragma unroll
    for (int i = 0; i < 32; i++) {
        int u = tid + i * 256;
        int n = u >> 6, c = u & 63;
        tile[n][c] = bias_table[rels[n] * 64 + c];
    }
    __syncthreads();

    __half2* g2 = reinterpret_cast<__half2*>(g_Wgh);
#pragma unroll
    for (int i = 0; i < 16; i++) {
        int u = tid + i * 256;
        int c = u >> 6, n2 = u & 63;
        int wq = c & 15, s = c >> 4;
        g2[(((wq * 4 + s) * N_DIM + m) << 7) + (n0 >> 1) + n2] =
            __floats2half2_rn(tile[2 * n2][c], tile[2 * n2 + 1][c]);
    }
}

// ---------------------------------------------------------------------------
// MMA / ldmatrix helpers
// ---------------------------------------------------------------------------
__device__ __forceinline__ void ldsm_x4(uint32_t* r, uint32_t addr) {
    asm volatile("ldmatrix.sync.aligned.m8n8.x4.shared.b16 {%0,%1,%2,%3}, [%4];"
        : "=r"(r[0]), "=r"(r[1]), "=r"(r[2]), "=r"(r[3]) : "r"(addr));
}
__device__ __forceinline__ void ldsm_x4_t(uint32_t* r, uint32_t addr) {
    asm volatile("ldmatrix.sync.aligned.m8n8.x4.trans.shared.b16 {%0,%1,%2,%3}, [%4];"
        : "=r"(r[0]), "=r"(r[1]), "=r"(r[2]), "=r"(r[3]) : "r"(addr));
}
__device__ __forceinline__ void hmma(float* d, const uint32_t* a, uint32_t b0, uint32_t b1) {
    asm volatile(
        "mma.sync.aligned.m16n8k16.row.col.f32.f16.f16.f32 "
        "{%0,%1,%2,%3},{%4,%5,%6,%7},{%8,%9},{%0,%1,%2,%3};"
        : "+f"(d[0]), "+f"(d[1]), "+f"(d[2]), "+f"(d[3])
        : "r"(a[0]), "r"(a[1]), "r"(a[2]), "r"(a[3]), "r"(b0), "r"(b1));
}
__device__ __forceinline__ uint32_t pack_h2(float lo, float hi) {
    __half2 h = __floats2half2_rn(lo, hi);
    return *reinterpret_cast<uint32_t*>(&h);
}
__device__ __forceinline__ uint32_t smem_u32(const void* p) {
    uint32_t a;
    asm("{ .reg .u64 t; cvta.to.shared.u64 t, %1; cvt.u32.u64 %0, t; }"
        : "=r"(a) : "l"(p));
    return a;
}

// ---------------------------------------------------------------------------
// Main kernel: CTA = bx -> (mh = bx&1, w = (bx>>1)&15, b = bx>>5).
// OUT tile M=128 x D=256. 512 thr.
// X: converted ONCE in prologue to resident smem [s][256k][64v] fp16
//    (rows 128B, swizzle c ^= k&7)  -- 128 KB.
// A: K chunks of 32, double-buffered cp.async [s][128m][32k] fp16
//    (rows 64B, swizzle q ^= (m>>1)&3) -- 2 x 32 KB.
// ---------------------------------------------------------------------------
#define AS_PLANE 8192
#define A_STAGE  32768
#define X_BASE   65536
#define XS_PLANE 32768
#define OUT_PITCH 260
#define SMEM_DYN (X_BASE + 4 * XS_PLANE)     // 196608

__global__ __launch_bounds__(512, 1) void pos_map_mm(
    const float* __restrict__ x, const float* __restrict__ token_bias,
    float* __restrict__ out)
{
    extern __shared__ __align__(16) char smem[];
    const int bx = blockIdx.x;
    const int m0 = (bx & 1) * 128, w = (bx >> 1) & 15, b = bx >> 5;
    const int tid = threadIdx.x, lane = tid & 31, warp = tid >> 5;
    const int wm = warp & 3;    // m-group: 32 rows
    const int wc = warp >> 2;   // s-plane
    const uint32_t sbase = smem_u32(smem);

    const __half* WgBase = g_Wgh + (size_t)(w * 4) * 65536 + (size_t)m0 * 256;
    const float4* xb4 = (const float4*)x + (size_t)(b * 16 + w) * (256 * 64);

    float acc[2][8][4];
#pragma unroll
    for (int mt = 0; mt < 2; mt++)
#pragma unroll
        for (int nt = 0; nt < 8; nt++)
#pragma unroll
            for (int j = 0; j < 4; j++) acc[mt][nt][j] = 0.f;

    const int grp  = lane >> 3;
    const int row8 = (grp & 1) * 8 + (lane & 7);
    const int qsel = grp >> 1;

    auto issue_A = [&](int st, int n0c) {
        // 2048 x 16B units: 4s x 128m x 4q
#pragma unroll
        for (int i = 0; i < 4; i++) {
            int u = tid + i * 512;
            int s = u >> 9, m = (u >> 2) & 127, q = u & 3;
            const __half* src = WgBase + s * 65536 + m * 256 + n0c + q * 8;
            uint32_t dst = sbase + st * A_STAGE + s * AS_PLANE + m * 64
                         + ((q ^ ((m >> 1) & 3)) << 4);
            asm volatile("cp.async.cg.shared.global [%0], [%1], 16;"
                         :: "r"(dst), "l"(src));
        }
        asm volatile("cp.async.commit_group;");
    };

    // ---- issue A chunk 0, then fill resident X while it flies ----
    issue_A(0, 0);

#pragma unroll
    for (int i = 0; i < 16; i++) {
        int u = tid + i * 512;                 // 8192 units: 256k x 32vp
        int k = u >> 5, vp = u & 31;
        float4 f0 = xb4[k * 64 + 2 * vp];
        float4 f1 = xb4[k * 64 + 2 * vp + 1];
        const float* p0 = reinterpret_cast<const float*>(&f0);
        const float* p1 = reinterpret_cast<const float*>(&f1);
        uint32_t off = X_BASE + (uint32_t)k * 128
                     + (((vp >> 2) ^ (k & 7)) << 4) + ((vp & 3) << 2);
#pragma unroll
        for (int s = 0; s < 4; s++)
            *(uint32_t*)(smem + off + s * XS_PLANE) = pack_h2(p0[s], p1[s]);
    }

    asm volatile("cp.async.wait_group 0;");
    __syncthreads();

    // ---- main loop: 8 A-chunks of 32 k ----
    for (int ch = 0; ch < 8; ch++) {
        const int st = ch & 1;
        if (ch < 7) issue_A((ch + 1) & 1, (ch + 1) * 32);

        const uint32_t sA = sbase + st * A_STAGE + wc * AS_PLANE;
        const uint32_t sX = sbase + X_BASE + wc * XS_PLANE;
#pragma unroll
        for (int ks = 0; ks < 2; ks++) {
            uint32_t a[2][4];
#pragma unroll
            for (int mt = 0; mt < 2; mt++) {
                int m = wm * 32 + mt * 16 + row8;
                int q = ks * 2 + qsel;
                ldsm_x4(a[mt], sA + m * 64 + ((q ^ ((m >> 1) & 3)) << 4));
            }
            uint32_t bq[4][4];
#pragma unroll
            for (int ng = 0; ng < 4; ng++) {
                int k = ch * 32 + ks * 16 + row8;
                int c = ng * 2 + qsel;
                ldsm_x4_t(bq[ng], sX + k * 128 + ((c ^ (k & 7)) << 4));
            }
#pragma unroll
            for (int mt = 0; mt < 2; mt++)
#pragma unroll
                for (int nt = 0; nt < 8; nt++)
                    hmma(acc[mt][nt], a[mt],
                         bq[nt >> 1][(nt & 1) * 2], bq[nt >> 1][(nt & 1) * 2 + 1]);
        }

        asm volatile("cp.async.wait_group 0;");
        __syncthreads();
    }

    // ---- epilogue: bias add, smem stage (reuses A/X region), f4 store ----
    float* so = (float*)smem;   // [128][OUT_PITCH] = 133120 B < SMEM_DYN
#pragma unroll
    for (int mt = 0; mt < 2; mt++)
#pragma unroll
        for (int j = 0; j < 2; j++) {
            int m = wm * 32 + mt * 16 + (lane >> 2) + j * 8;
            float tb = token_bias[(w * 4 + wc) * 256 + m0 + m];
            float* dr = so + m * OUT_PITCH + wc;
#pragma unroll
            for (int nt = 0; nt < 8; nt++) {
                int v = nt * 8 + ((lane & 3) << 1);
                dr[v * 4]       = acc[mt][nt][j * 2 + 0] + tb;
                dr[(v + 1) * 4] = acc[mt][nt][j * 2 + 1] + tb;
            }
        }
    __syncthreads();

    float4* ob = (float4*)(out + (size_t)((b * 16 + w) * 256 + m0) * 256);
#pragma unroll
    for (int i = 0; i < 16; i++) {
        int u = tid + i * 512;
        int row = u >> 6, c = u & 63;
        ob[row * 64 + c] = *(float4*)(so + row * OUT_PITCH + c * 4);
    }
}

// ---------------------------------------------------------------------------
// Launch: inputs in metadata order: x, bias_table, token_bias, rel_index
// ---------------------------------------------------------------------------
extern "C" void kernel_launch(void* const* d_in, const int* in_sizes, int n_in,
                              void* d_out, int out_size)
{
    const float* x          = (const float*)d_in[0];
    const float* bias_table = (const float*)d_in[1];
    const float* token_bias = (const float*)d_in[2];
    const int*   rel_index  = (const int*)d_in[3];
    float* out = (float*)d_out;
    (void)in_sizes; (void)n_in; (void)out_size;

    cudaFuncSetAttribute(pos_map_mm,
                         cudaFuncAttributeMaxDynamicSharedMemorySize, SMEM_DYN);

    build_weights<<<dim3(256, 2), 256>>>(bias_table, rel_index);
    pos_map_mm<<<1024, 512, SMEM_DYN>>>(x, token_bias, out);
}